// round 15
// baseline (speedup 1.0000x reference)
#include <cuda_runtime.h>
#include <cstdint>

#define S_LEN   2048
#define HID     1024
#define NHEAD   16
#define HDIM    64
#define NBATCH  2
#define M_ROWS  (NBATCH * S_LEN)      // 4096
#define BH      (NBATCH * NHEAD)      // 32

// Scratch (device globals; ONLY referenced from device code)
__device__ float g_Q[(size_t)BH * S_LEN * HDIM];
__device__ float g_V[(size_t)BH * S_LEN * HDIM];
__device__ float g_At[(size_t)M_ROWS * HID];        // tf32-rounded hidden
__device__ float g_Wt[2 * (size_t)HID * HID];       // tf32-rounded Wq, Wv

// ---------------------------------------------------------------------------
// tf32 helpers
// ---------------------------------------------------------------------------
__device__ __forceinline__ uint4 rna4(float4 v) {
    uint4 u;
    asm("cvt.rna.tf32.f32 %0, %1;" : "=r"(u.x) : "f"(v.x));
    asm("cvt.rna.tf32.f32 %0, %1;" : "=r"(u.y) : "f"(v.y));
    asm("cvt.rna.tf32.f32 %0, %1;" : "=r"(u.z) : "f"(v.z));
    asm("cvt.rna.tf32.f32 %0, %1;" : "=r"(u.w) : "f"(v.w));
    return u;
}
__device__ __forceinline__ uint32_t rna1(float v) {
    uint32_t u;
    asm("cvt.rna.tf32.f32 %0, %1;" : "=r"(u) : "f"(v));
    return u;
}

// Fused tf32 rounding pre-pass: [A | Wq | Wv], 4 float4 per thread.
#define NA4 (M_ROWS * HID / 4)          // 1048576
#define NW4 (HID * HID / 4)             // 262144
#define NT4 (NA4 + 2 * NW4)             // 1572864 float4s total
__global__ void conv_all_tf32(const float* __restrict__ A,
                              const float* __restrict__ Wq,
                              const float* __restrict__ Wv)
{
    const size_t i0 = (size_t)blockIdx.x * 1024 + threadIdx.x;
    const float4* src[4];
    uint4* dst[4];
#pragma unroll
    for (int it = 0; it < 4; it++) {
        size_t i = i0 + it * 256;
        if (i < NA4) {
            src[it] = (const float4*)A + i;
            dst[it] = (uint4*)g_At + i;
        } else if (i < NA4 + NW4) {
            src[it] = (const float4*)Wq + (i - NA4);
            dst[it] = (uint4*)g_Wt + (i - NA4);
        } else {
            src[it] = (const float4*)Wv + (i - NA4 - NW4);
            dst[it] = (uint4*)g_Wt + (i - NA4);   // second W block contiguous
        }
    }
    float4 v[4];
#pragma unroll
    for (int it = 0; it < 4; it++) v[it] = *src[it];
#pragma unroll
    for (int it = 0; it < 4; it++) *dst[it] = rna4(v[it]);
}

// ---------------------------------------------------------------------------
// Heterogeneous projection GEMM: tensor + fp32 pipes concurrently.
//   blockIdx.x < 7 : tf32 mma path, 128x128 tile, cols [x*128, x*128+128)
//   blockIdx.x >= 7: FFMA path, 64x64 tile, cols [896, 1024), RAW fp32 inputs
// __launch_bounds__(256,2): both CTA types co-reside 2/SM so the mma CTA's
// tensor stream overlaps the FFMA CTA's fp32 stream.
// ---------------------------------------------------------------------------
#define BKG 32
#define APITCH 36
#define BPITCH 136
#define ABUF (128 * APITCH)
#define BBUF (32 * BPITCH)
#define PROJ_SMEM ((2 * ABUF + 2 * BBUF) * 4)       // 71680 B

__device__ __forceinline__ uint32_t smem_u32(const void* p) {
    uint32_t a;
    asm("{ .reg .u64 t; cvta.to.shared.u64 t, %1; cvt.u32.u64 %0, t; }"
        : "=r"(a) : "l"(p));
    return a;
}

#define CP16(dst, src) \
    asm volatile("cp.async.cg.shared.global [%0], [%1], 16;" \
                 :: "r"(dst), "l"(src) : "memory")
#define CP_COMMIT() asm volatile("cp.async.commit_group;" ::: "memory")
#define CP_WAIT1()  asm volatile("cp.async.wait_group 1;" ::: "memory")
#define CP_WAIT0()  asm volatile("cp.async.wait_group 0;" ::: "memory")

#define MMA_TF32(c, a0, a1, a2, a3, b0, b1)                                   \
    asm volatile("mma.sync.aligned.m16n8k8.row.col.f32.tf32.tf32.f32 "        \
        "{%0,%1,%2,%3}, {%4,%5,%6,%7}, {%8,%9}, {%0,%1,%2,%3};"               \
        : "+f"((c)[0]), "+f"((c)[1]), "+f"((c)[2]), "+f"((c)[3])              \
        : "r"(a0), "r"(a1), "r"(a2), "r"(a3), "r"(b0), "r"(b1))

__global__ __launch_bounds__(256, 2)
void proj_mma(const float* __restrict__ Araw,
              const float* __restrict__ Wqr, const float* __restrict__ Wvr,
              const float* __restrict__ bq, const float* __restrict__ bv)
{
    extern __shared__ float smp[];

    const int tid = threadIdx.x;
    const int z  = blockIdx.z;
    const float* bias = z ? bv : bq;
    float*       Out  = z ? g_V : g_Q;

    // ================= FFMA path (cols 896..1023, raw fp32) =================
    if (blockIdx.x >= 7) {
        const int sub = blockIdx.x - 7;                   // 0..3
        const int m0f = blockIdx.y * 128 + (sub >> 1) * 64;
        const int n0f = 896 + (sub & 1) * 64;
        const float* Wr = z ? Wvr : Wqr;

        float* Af = smp;              // [16][68]  (k-major)
        float* Bf = smp + 16 * 68;    // [16][68]

        const int r  = tid >> 2, kc = (tid & 3) * 4;      // A loader
        const int kb = tid >> 4, cb = (tid & 15) * 4;     // B loader
        const int ty = tid >> 4, tx = tid & 15;           // 4x4 compute tile

        float facc[4][4];
#pragma unroll
        for (int i = 0; i < 4; i++)
#pragma unroll
            for (int j = 0; j < 4; j++) facc[i][j] = 0.f;

        float4 pa = *(const float4*)&Araw[(size_t)(m0f + r) * HID + kc];
        float4 pb = *(const float4*)&Wr[(size_t)kb * HID + n0f + cb];

        for (int s = 0; s < 64; s++) {
            Af[(kc + 0) * 68 + r] = pa.x;
            Af[(kc + 1) * 68 + r] = pa.y;
            Af[(kc + 2) * 68 + r] = pa.z;
            Af[(kc + 3) * 68 + r] = pa.w;
            *(float4*)&Bf[kb * 68 + cb] = pb;
            __syncthreads();
            if (s < 63) {
                const int k0 = (s + 1) * 16;
                pa = *(const float4*)&Araw[(size_t)(m0f + r) * HID + k0 + kc];
                pb = *(const float4*)&Wr[(size_t)(k0 + kb) * HID + n0f + cb];
            }
#pragma unroll
            for (int k = 0; k < 16; k++) {
                float4 a4 = *(const float4*)&Af[k * 68 + ty * 4];
                float4 b4 = *(const float4*)&Bf[k * 68 + tx * 4];
                float av[4] = {a4.x, a4.y, a4.z, a4.w};
                float bv2[4] = {b4.x, b4.y, b4.z, b4.w};
#pragma unroll
                for (int i = 0; i < 4; i++)
#pragma unroll
                    for (int j = 0; j < 4; j++)
                        facc[i][j] += av[i] * bv2[j];
            }
            __syncthreads();
        }

        const float4 b4 = *(const float4*)&bias[n0f + tx * 4];
        const int h = (n0f + tx * 4) >> 6;
        const int d = (n0f + tx * 4) & 63;
#pragma unroll
        for (int i = 0; i < 4; i++) {
            const int m = m0f + ty * 4 + i;
            const int bb = m >> 11, sr = m & (S_LEN - 1);
            float4 o = {facc[i][0] + b4.x, facc[i][1] + b4.y,
                        facc[i][2] + b4.z, facc[i][3] + b4.w};
            *(float4*)&Out[((size_t)((bb * NHEAD + h) * S_LEN + sr)) * HDIM + d] = o;
        }
        return;
    }

    // ================= tf32 mma path (cols 0..895) =================
    float* Asm = smp;                       // [2][128][APITCH]
    float* Bsm = smp + 2 * ABUF;            // [2][32][BPITCH]

    const int n0 = blockIdx.x * 128;
    const int m0 = blockIdx.y * 128;
    const float* Wg = g_Wt + (size_t)z * HID * HID;

    const uint32_t sA = smem_u32(Asm);
    const uint32_t sB = smem_u32(Bsm);

    auto load_stage = [&](int s, int buf) {
        const int k0 = s * BKG;
        const uint32_t aB = sA + buf * ABUF * 4;
        const uint32_t bB = sB + buf * BBUF * 4;
#pragma unroll
        for (int it = 0; it < 4; it++) {
            int idx = tid + it * 256;
            int r = idx >> 3, c = idx & 7;
            CP16(aB + (r * APITCH + c * 4) * 4,
                 &g_At[(size_t)(m0 + r) * HID + k0 + c * 4]);
        }
#pragma unroll
        for (int it = 0; it < 4; it++) {
            int idx = tid + it * 256;
            int k = idx >> 5, c = idx & 31;
            CP16(bB + (k * BPITCH + c * 4) * 4,
                 &Wg[(size_t)(k0 + k) * HID + n0 + c * 4]);
        }
        CP_COMMIT();
    };

    const int wid = tid >> 5, lane = tid & 31;
    const int wm = (wid & 1) * 64;
    const int wn = (wid >> 1) * 32;
    const int lg = lane >> 2, lq = lane & 3;

    float acc[4][4][4];
#pragma unroll
    for (int mt = 0; mt < 4; mt++)
#pragma unroll
        for (int nt = 0; nt < 4; nt++)
#pragma unroll
            for (int e = 0; e < 4; e++) acc[mt][nt][e] = 0.f;

    auto compute_stage = [&](int buf) {
        const float* Ab = Asm + buf * ABUF;
        const float* Bb = Bsm + buf * BBUF;
#pragma unroll
        for (int ks = 0; ks < 4; ks++) {
            const int kb = ks * 8;
            uint32_t b0[4], b1[4];
#pragma unroll
            for (int nt = 0; nt < 4; nt++) {
                const int n = wn + nt * 8 + lg;
                b0[nt] = __float_as_uint(Bb[(kb + lq) * BPITCH + n]);
                b1[nt] = __float_as_uint(Bb[(kb + lq + 4) * BPITCH + n]);
            }
#pragma unroll
            for (int mt = 0; mt < 4; mt++) {
                const float* ar = Ab + (wm + mt * 16 + lg) * APITCH + kb + lq;
                uint32_t a0 = __float_as_uint(ar[0]);
                uint32_t a1 = __float_as_uint(ar[8 * APITCH]);
                uint32_t a2 = __float_as_uint(ar[4]);
                uint32_t a3 = __float_as_uint(ar[8 * APITCH + 4]);
#pragma unroll
                for (int nt = 0; nt < 4; nt++)
                    MMA_TF32(acc[mt][nt], a0, a1, a2, a3, b0[nt], b1[nt]);
            }
        }
    };

    load_stage(0, 0);
    load_stage(1, 1);
    const int NST = HID / BKG;              // 32
    for (int s = 0; s < NST; s++) {
        if (s < NST - 1) CP_WAIT1(); else CP_WAIT0();
        __syncthreads();
        compute_stage(s & 1);
        __syncthreads();
        if (s + 2 < NST) load_stage(s + 2, s & 1);
    }

#pragma unroll
    for (int mt = 0; mt < 4; mt++) {
        const int mA = m0 + wm + mt * 16 + lg;
        const int mB = mA + 8;
#pragma unroll
        for (int nt = 0; nt < 4; nt++) {
            const int n = n0 + wn + nt * 8 + lq * 2;
            const float2 b2 = *(const float2*)&bias[n];
            const int h = n >> 6, d = n & 63;
            {
                int bb = mA >> 11, sr = mA & (S_LEN - 1);
                float2 o = {acc[mt][nt][0] + b2.x, acc[mt][nt][1] + b2.y};
                *(float2*)&Out[((size_t)((bb * NHEAD + h) * S_LEN + sr)) * HDIM + d] = o;
            }
            {
                int bb = mB >> 11, sr = mB & (S_LEN - 1);
                float2 o = {acc[mt][nt][2] + b2.x, acc[mt][nt][3] + b2.y};
                *(float2*)&Out[((size_t)((bb * NHEAD + h) * S_LEN + sr)) * HDIM + d] = o;
            }
        }
    }
}

// ---------------------------------------------------------------------------
// Attention v5b (R14 exact: best measured, ~77us). 64-query CTAs, 512 threads,
// compact band P, 2 CTAs/SM, V-load hoisted before softmax.
// ---------------------------------------------------------------------------
#define QPITCH 68
#define VPITCH4 72
#define PPITCH4 148
#define QV4_FLOATS (192 * VPITCH4)          // 13824
#define ATTN4_FLOATS (64 * PPITCH4 + QV4_FLOATS + 192 + 15 * 64 + 64)
#define ATTN4_SMEM (ATTN4_FLOATS * 4)       // 98048 B

__global__ __launch_bounds__(512, 2)
void attn_mma(const float* __restrict__ am, float* __restrict__ out)
{
    extern __shared__ float sm3[];
    float* P    = sm3;                        // [64][148] compact band
    float* QV   = sm3 + 64 * PPITCH4;         // Qs[192][68] then Vs[192][72]
    float* ams  = QV + QV4_FLOATS;            // [192]
    float* sstr = ams + 192;                  // [15][64]
    float* sinv = sstr + 15 * 64;             // [64]

    const int i0 = blockIdx.x * 64;
    const int bh = blockIdx.y;
    const int b  = bh >> 4;
    const int h  = bh & 15;

    const float* Qg  = g_Q + (size_t)bh * S_LEN * HDIM;
    const float* Vg  = g_V + (size_t)bh * S_LEN * HDIM;
    const float* amb = am + (size_t)b * S_LEN;

    const int j0   = (i0 >= 128) ? (i0 - 128) : 0;
    const int Wn   = i0 + 64 - j0;            // 64,128,192
    const int qoff = i0 - j0;                 // min(i0,128)
    const int nstr = (i0 >= 256) ? (i0 / 128 - 1) : 0;
    const int base = i0 & 127;                // 0 or 64 (strided residue base)

    const int tid = threadIdx.x;

    // ---- Q window -> smem (tf32), pitch 68; mask row -> smem ----
    for (int idx = tid; idx < Wn * 16; idx += 512) {
        int r = idx >> 4, c = (idx & 15) * 4;
        *(uint4*)&QV[r * QPITCH + c] =
            rna4(*(const float4*)&Qg[(size_t)(j0 + r) * HDIM + c]);
    }
    for (int idx = tid; idx < Wn; idx += 512) ams[idx] = amb[j0 + idx];
    __syncthreads();

    const int wid = tid >> 5, lane = tid & 31;
    const int g  = lane >> 2, lq = lane & 3;
    const int jgrp = wid >> 2, sb = wid & 3;
    const int r0 = jgrp * 16;
    const int t_lo = (qoff + r0 - 128) >> 3;
    const int rowA = qoff + r0 + g;
    const int NTW   = (sb < 2) ? 5 : 4;
    const int ubase = (sb < 2) ? sb * 5 : 10 + (sb - 2) * 4;

    const float* Qs = QV;

    // ---- phase A: S band tiles (5/5/4/4 per warp) -> compact P ----
    {
        float acc[5][4];
#pragma unroll
        for (int u = 0; u < 5; u++)
#pragma unroll
            for (int e = 0; e < 4; e++) acc[u][e] = 0.f;

#pragma unroll
        for (int kd = 0; kd < 8; kd++) {
            const int k = kd * 8 + lq;
            uint32_t a0 = __float_as_uint(Qs[rowA * QPITCH + k]);
            uint32_t a1 = __float_as_uint(Qs[(rowA + 8) * QPITCH + k]);
            uint32_t a2 = __float_as_uint(Qs[rowA * QPITCH + k + 4]);
            uint32_t a3 = __float_as_uint(Qs[(rowA + 8) * QPITCH + k + 4]);
#pragma unroll
            for (int u = 0; u < 5; u++) {
                const int t = t_lo + ubase + u;
                if (u < NTW && t >= 0) {
                    const int kr = t * 8 + g;
                    uint32_t b0 = __float_as_uint(Qs[kr * QPITCH + k]);
                    uint32_t b1 = __float_as_uint(Qs[kr * QPITCH + k + 4]);
                    MMA_TF32(acc[u], a0, a1, a2, a3, b0, b1);
                }
            }
        }
#pragma unroll
        for (int u = 0; u < 5; u++) {
            const int t = t_lo + ubase + u;
            if (u < NTW && t >= 0) {
                const int cabs = t * 8 + 2 * lq;           // window col
                const int cc   = (ubase + u) * 8 + 2 * lq; // compact col
                const float a0m = ams[cabs], a1m = ams[cabs + 1];
                float2 w0 = {acc[u][0] * 0.125f + a0m, acc[u][1] * 0.125f + a1m};
                float2 w1 = {acc[u][2] * 0.125f + a0m, acc[u][3] * 0.125f + a1m};
                *(float2*)&P[(r0 + g) * PPITCH4 + cc]     = w0;
                *(float2*)&P[(r0 + g + 8) * PPITCH4 + cc] = w1;
            }
        }
    }

    // ---- phase B: strided scores (8 lanes per row) ----
    const int rB  = tid >> 3;                 // 0..63
    const int qB8 = tid & 7;                  // 0..7
    {
        const float4* qp = (const float4*)&Qs[(qoff + rB) * QPITCH + qB8 * 8];
        const float4 qa = qp[0], qb = qp[1];  // loop-invariant, hoisted
        for (int k = 0; k < nstr; k++) {
            const int jb = base + rB + 128 * k;
            const float4* kp = (const float4*)&Qg[(size_t)jb * HDIM + qB8 * 8];
            float4 kb4 = kp[0];
            float s = qa.x * kb4.x + qa.y * kb4.y + qa.z * kb4.z + qa.w * kb4.w;
            float4 kc4 = kp[1];
            s += qb.x * kc4.x + qb.y * kc4.y + qb.z * kc4.z + qb.w * kc4.w;
            s += __shfl_xor_sync(0xFFFFFFFFu, s, 1);
            s += __shfl_xor_sync(0xFFFFFFFFu, s, 2);
            s += __shfl_xor_sync(0xFFFFFFFFu, s, 4);
            if (qB8 == 0) sstr[k * 64 + rB] = s * 0.125f + amb[jb];
        }
    }
    __syncthreads();

    // ---- V window -> smem (tf32), pitch 72 (hoisted; overlaps softmax) ----
    for (int idx = tid; idx < Wn * 16; idx += 512) {
        int r = idx >> 4, c = (idx & 15) * 4;
        *(uint4*)&QV[r * VPITCH4 + c] =
            rna4(*(const float4*)&Vg[(size_t)(j0 + r) * HDIM + c]);
    }

    // ---- phase C: softmax over compact band + strided ----
    {
        const int r   = rB;
        const int tlg = (qoff + (r & ~15) - 128) >> 3;
        const int off0 = max(0, qoff + r - 128) - tlg * 8;  // compact allowed lo
        const int off1 = (qoff + r) - tlg * 8;              // compact allowed hi
        const int vlo  = max(0, -tlg * 8);                  // first t>=0 col
        float* Pr = &P[r * PPITCH4];

        float mx = -1e30f;
        for (int c = off0 + ((qB8 - off0) & 7); c <= off1; c += 8)
            mx = fmaxf(mx, Pr[c]);
        for (int k = qB8; k < nstr; k += 8) mx = fmaxf(mx, sstr[k * 64 + r]);
        mx = fmaxf(mx, __shfl_xor_sync(0xFFFFFFFFu, mx, 1));
        mx = fmaxf(mx, __shfl_xor_sync(0xFFFFFFFFu, mx, 2));
        mx = fmaxf(mx, __shfl_xor_sync(0xFFFFFFFFu, mx, 4));

        float sum = 0.f;
        for (int c = vlo + ((qB8 - vlo) & 7); c < 144; c += 8) {
            float v = Pr[c];
            float p = (c >= off0 && c <= off1) ? __expf(v - mx) : 0.f;
            Pr[c] = __uint_as_float(rna1(p));
            sum += p;
        }
        for (int k = qB8; k < nstr; k += 8) {
            float p = __expf(sstr[k * 64 + r] - mx);
            sstr[k * 64 + r] = p;
            sum += p;
        }
        sum += __shfl_xor_sync(0xFFFFFFFFu, sum, 1);
        sum += __shfl_xor_sync(0xFFFFFFFFu, sum, 2);
        sum += __shfl_xor_sync(0xFFFFFFFFu, sum, 4);
        if (qB8 == 0) sinv[r] = 1.0f / sum;
    }
    __syncthreads();

    // ---- phase D: PV (2 n8-tiles per warp over 18 compact k-tiles) ----
    const float* Vs = QV;
    float oacc[2][4];
#pragma unroll
    for (int nt = 0; nt < 2; nt++)
#pragma unroll
        for (int e = 0; e < 4; e++) oacc[nt][e] = 0.f;

#pragma unroll
    for (int u = 0; u < 18; u++) {
        const int t = t_lo + u;
        if (t >= 0) {
            const int cc = u * 8;                 // compact k base
            const int kb = t * 8;                 // window k base
            uint32_t a0 = __float_as_uint(P[(r0 + g) * PPITCH4 + cc + lq]);
            uint32_t a1 = __float_as_uint(P[(r0 + g + 8) * PPITCH4 + cc + lq]);
            uint32_t a2 = __float_as_uint(P[(r0 + g) * PPITCH4 + cc + lq + 4]);
            uint32_t a3 = __float_as_uint(P[(r0 + g + 8) * PPITCH4 + cc + lq + 4]);
#pragma unroll
            for (int nt = 0; nt < 2; nt++) {
                const int ncol = sb * 16 + nt * 8 + g;
                uint32_t b0 = __float_as_uint(Vs[(kb + lq) * VPITCH4 + ncol]);
                uint32_t b1 = __float_as_uint(Vs[(kb + lq + 4) * VPITCH4 + ncol]);
                MMA_TF32(oacc[nt], a0, a1, a2, a3, b0, b1);
            }
        }
    }

    // strided PV (scalar, V from global fp32; warp covers its 16 cols)
    for (int k = 0; k < nstr; k++) {
        const float p0 = sstr[k * 64 + r0 + g];
        const float p1 = sstr[k * 64 + r0 + g + 8];
        const float* v0 = &Vg[(size_t)(base + r0 + g + 128 * k) * HDIM];
        const float* v1 = v0 + 8 * HDIM;
#pragma unroll
        for (int nt = 0; nt < 2; nt++) {
            const int n = sb * 16 + nt * 8 + 2 * lq;
            float2 x0 = *(const float2*)&v0[n];
            float2 x1 = *(const float2*)&v1[n];
            oacc[nt][0] += p0 * x0.x; oacc[nt][1] += p0 * x0.y;
            oacc[nt][2] += p1 * x1.x; oacc[nt][3] += p1 * x1.y;
        }
    }

    // ---- epilogue ----
    const float inv0 = sinv[r0 + g];
    const float inv1 = sinv[r0 + g + 8];
    const int iA = i0 + r0 + g;
    float* oA = &out[((size_t)(b * S_LEN + iA)) * HID + h * HDIM + sb * 16];
    float* oB = oA + 8 * HID;
#pragma unroll
    for (int nt = 0; nt < 2; nt++) {
        const int n = nt * 8 + 2 * lq;
        float2 w0 = {oacc[nt][0] * inv0, oacc[nt][1] * inv0};
        float2 w1 = {oacc[nt][2] * inv1, oacc[nt][3] * inv1};
        *(float2*)&oA[n] = w0;
        *(float2*)&oB[n] = w1;
    }
}

// ---------------------------------------------------------------------------
extern "C" void kernel_launch(void* const* d_in, const int* in_sizes, int n_in,
                              void* d_out, int out_size)
{
    const float* hidden = (const float*)d_in[0];
    const float* am     = (const float*)d_in[1];
    const float* Wq     = (const float*)d_in[2];
    const float* bq     = (const float*)d_in[3];
    const float* Wv     = (const float*)d_in[4];
    const float* bv     = (const float*)d_in[5];
    float* out = (float*)d_out;

    (void)in_sizes; (void)n_in; (void)out_size;

    cudaFuncSetAttribute(proj_mma,
                         cudaFuncAttributeMaxDynamicSharedMemorySize, PROJ_SMEM);
    cudaFuncSetAttribute(attn_mma,
                         cudaFuncAttributeMaxDynamicSharedMemorySize, ATTN4_SMEM);

    // fused tf32 rounding pre-pass
    conv_all_tf32<<<NT4 / 1024, 256>>>(hidden, Wq, Wv);

    // heterogeneous projection: 7 mma n-tiles + 4 FFMA subtiles per (y,z)
    dim3 gp(11, M_ROWS / 128, 2);
    proj_mma<<<gp, 256, PROJ_SMEM>>>(hidden, Wq, Wv, bq, bv);

    dim3 ga(S_LEN / 64, BH);
    attn_mma<<<ga, 512, ATTN4_SMEM>>>(am, out);
}

// round 16
// speedup vs baseline: 1.2139x; 1.2139x over previous
#include <cuda_runtime.h>
#include <cstdint>

#define S_LEN   2048
#define HID     1024
#define NHEAD   16
#define HDIM    64
#define NBATCH  2
#define M_ROWS  (NBATCH * S_LEN)      // 4096
#define BH      (NBATCH * NHEAD)      // 32

// Scratch (device globals; ONLY referenced from device code)
__device__ float g_Q[(size_t)BH * S_LEN * HDIM];
__device__ float g_V[(size_t)BH * S_LEN * HDIM];
__device__ float g_At[(size_t)M_ROWS * HID];        // tf32-rounded hidden
__device__ float g_Wt[2 * (size_t)HID * HID];       // tf32-rounded Wq, Wv

// ---------------------------------------------------------------------------
// tf32 helpers
// ---------------------------------------------------------------------------
__device__ __forceinline__ uint4 rna4(float4 v) {
    uint4 u;
    asm("cvt.rna.tf32.f32 %0, %1;" : "=r"(u.x) : "f"(v.x));
    asm("cvt.rna.tf32.f32 %0, %1;" : "=r"(u.y) : "f"(v.y));
    asm("cvt.rna.tf32.f32 %0, %1;" : "=r"(u.z) : "f"(v.z));
    asm("cvt.rna.tf32.f32 %0, %1;" : "=r"(u.w) : "f"(v.w));
    return u;
}
__device__ __forceinline__ uint32_t rna1(float v) {
    uint32_t u;
    asm("cvt.rna.tf32.f32 %0, %1;" : "=r"(u) : "f"(v));
    return u;
}

// Fused tf32 rounding pre-pass: [A | Wq | Wv], 4 float4 per thread.
#define NA4 (M_ROWS * HID / 4)          // 1048576
#define NW4 (HID * HID / 4)             // 262144
#define NT4 (NA4 + 2 * NW4)             // 1572864 float4s total
__global__ void conv_all_tf32(const float* __restrict__ A,
                              const float* __restrict__ Wq,
                              const float* __restrict__ Wv)
{
    const size_t i0 = (size_t)blockIdx.x * 1024 + threadIdx.x;
    const float4* src[4];
    uint4* dst[4];
#pragma unroll
    for (int it = 0; it < 4; it++) {
        size_t i = i0 + it * 256;
        if (i < NA4) {
            src[it] = (const float4*)A + i;
            dst[it] = (uint4*)g_At + i;
        } else if (i < NA4 + NW4) {
            src[it] = (const float4*)Wq + (i - NA4);
            dst[it] = (uint4*)g_Wt + (i - NA4);
        } else {
            src[it] = (const float4*)Wv + (i - NA4 - NW4);
            dst[it] = (uint4*)g_Wt + (i - NA4);   // second W block contiguous
        }
    }
    float4 v[4];
#pragma unroll
    for (int it = 0; it < 4; it++) v[it] = *src[it];
#pragma unroll
    for (int it = 0; it < 4; it++) *dst[it] = rna4(v[it]);
}

// ---------------------------------------------------------------------------
// tf32 mma.sync projection GEMM (confirmed at legacy tf32 mma HW ceiling
// ~112us: pipeline-depth, occupancy, and pipe-heterogeneity all falsified)
// ---------------------------------------------------------------------------
#define BKG 32
#define APITCH 36
#define BPITCH 136
#define ABUF (128 * APITCH)
#define BBUF (32 * BPITCH)
#define PROJ_SMEM ((2 * ABUF + 2 * BBUF) * 4)       // 71680 B

__device__ __forceinline__ uint32_t smem_u32(const void* p) {
    uint32_t a;
    asm("{ .reg .u64 t; cvta.to.shared.u64 t, %1; cvt.u32.u64 %0, t; }"
        : "=r"(a) : "l"(p));
    return a;
}

#define CP16(dst, src) \
    asm volatile("cp.async.cg.shared.global [%0], [%1], 16;" \
                 :: "r"(dst), "l"(src) : "memory")
#define CP_COMMIT() asm volatile("cp.async.commit_group;" ::: "memory")
#define CP_WAIT1()  asm volatile("cp.async.wait_group 1;" ::: "memory")
#define CP_WAIT0()  asm volatile("cp.async.wait_group 0;" ::: "memory")

#define MMA_TF32(c, a0, a1, a2, a3, b0, b1)                                   \
    asm volatile("mma.sync.aligned.m16n8k8.row.col.f32.tf32.tf32.f32 "        \
        "{%0,%1,%2,%3}, {%4,%5,%6,%7}, {%8,%9}, {%0,%1,%2,%3};"               \
        : "+f"((c)[0]), "+f"((c)[1]), "+f"((c)[2]), "+f"((c)[3])              \
        : "r"(a0), "r"(a1), "r"(a2), "r"(a3), "r"(b0), "r"(b1))

__global__ __launch_bounds__(256)
void proj_mma(const float* __restrict__ bq, const float* __restrict__ bv)
{
    extern __shared__ float smp[];
    float* Asm = smp;                       // [2][128][APITCH]
    float* Bsm = smp + 2 * ABUF;            // [2][32][BPITCH]

    const int tid = threadIdx.x;
    const int z  = blockIdx.z;
    const int n0 = blockIdx.x * 128;
    const int m0 = blockIdx.y * 128;

    const float* Wg   = g_Wt + (size_t)z * HID * HID;
    const float* bias = z ? bv : bq;
    float*       Out  = z ? g_V : g_Q;

    const uint32_t sA = smem_u32(Asm);
    const uint32_t sB = smem_u32(Bsm);

    auto load_stage = [&](int s, int buf) {
        const int k0 = s * BKG;
        const uint32_t aB = sA + buf * ABUF * 4;
        const uint32_t bB = sB + buf * BBUF * 4;
#pragma unroll
        for (int it = 0; it < 4; it++) {
            int idx = tid + it * 256;
            int r = idx >> 3, c = idx & 7;
            CP16(aB + (r * APITCH + c * 4) * 4,
                 &g_At[(size_t)(m0 + r) * HID + k0 + c * 4]);
        }
#pragma unroll
        for (int it = 0; it < 4; it++) {
            int idx = tid + it * 256;
            int k = idx >> 5, c = idx & 31;
            CP16(bB + (k * BPITCH + c * 4) * 4,
                 &Wg[(size_t)(k0 + k) * HID + n0 + c * 4]);
        }
        CP_COMMIT();
    };

    const int wid = tid >> 5, lane = tid & 31;
    const int wm = (wid & 1) * 64;
    const int wn = (wid >> 1) * 32;
    const int lg = lane >> 2, lq = lane & 3;

    float acc[4][4][4];
#pragma unroll
    for (int mt = 0; mt < 4; mt++)
#pragma unroll
        for (int nt = 0; nt < 4; nt++)
#pragma unroll
            for (int e = 0; e < 4; e++) acc[mt][nt][e] = 0.f;

    auto compute_stage = [&](int buf) {
        const float* Ab = Asm + buf * ABUF;
        const float* Bb = Bsm + buf * BBUF;
#pragma unroll
        for (int ks = 0; ks < 4; ks++) {
            const int kb = ks * 8;
            uint32_t b0[4], b1[4];
#pragma unroll
            for (int nt = 0; nt < 4; nt++) {
                const int n = wn + nt * 8 + lg;
                b0[nt] = __float_as_uint(Bb[(kb + lq) * BPITCH + n]);
                b1[nt] = __float_as_uint(Bb[(kb + lq + 4) * BPITCH + n]);
            }
#pragma unroll
            for (int mt = 0; mt < 4; mt++) {
                const float* ar = Ab + (wm + mt * 16 + lg) * APITCH + kb + lq;
                uint32_t a0 = __float_as_uint(ar[0]);
                uint32_t a1 = __float_as_uint(ar[8 * APITCH]);
                uint32_t a2 = __float_as_uint(ar[4]);
                uint32_t a3 = __float_as_uint(ar[8 * APITCH + 4]);
#pragma unroll
                for (int nt = 0; nt < 4; nt++)
                    MMA_TF32(acc[mt][nt], a0, a1, a2, a3, b0[nt], b1[nt]);
            }
        }
    };

    load_stage(0, 0);
    load_stage(1, 1);
    const int NST = HID / BKG;              // 32
    for (int s = 0; s < NST; s++) {
        if (s < NST - 1) CP_WAIT1(); else CP_WAIT0();
        __syncthreads();
        compute_stage(s & 1);
        __syncthreads();
        if (s + 2 < NST) load_stage(s + 2, s & 1);
    }

#pragma unroll
    for (int mt = 0; mt < 4; mt++) {
        const int mA = m0 + wm + mt * 16 + lg;
        const int mB = mA + 8;
#pragma unroll
        for (int nt = 0; nt < 4; nt++) {
            const int n = n0 + wn + nt * 8 + lq * 2;
            const float2 b2 = *(const float2*)&bias[n];
            const int h = n >> 6, d = n & 63;
            {
                int bb = mA >> 11, sr = mA & (S_LEN - 1);
                float2 o = {acc[mt][nt][0] + b2.x, acc[mt][nt][1] + b2.y};
                *(float2*)&Out[((size_t)((bb * NHEAD + h) * S_LEN + sr)) * HDIM + d] = o;
            }
            {
                int bb = mB >> 11, sr = mB & (S_LEN - 1);
                float2 o = {acc[mt][nt][2] + b2.x, acc[mt][nt][3] + b2.y};
                *(float2*)&Out[((size_t)((bb * NHEAD + h) * S_LEN + sr)) * HDIM + d] = o;
            }
        }
    }
}

// ---------------------------------------------------------------------------
// Attention v5b (best measured: ~77us). 64-query CTAs, 512 threads, compact
// band P, 2 CTAs/SM, V-load hoisted before softmax.
// ---------------------------------------------------------------------------
#define QPITCH 68
#define VPITCH4 72
#define PPITCH4 148
#define QV4_FLOATS (192 * VPITCH4)          // 13824
#define ATTN4_FLOATS (64 * PPITCH4 + QV4_FLOATS + 192 + 15 * 64 + 64)
#define ATTN4_SMEM (ATTN4_FLOATS * 4)       // 98048 B

__global__ __launch_bounds__(512, 2)
void attn_mma(const float* __restrict__ am, float* __restrict__ out)
{
    extern __shared__ float sm3[];
    float* P    = sm3;                        // [64][148] compact band
    float* QV   = sm3 + 64 * PPITCH4;         // Qs[192][68] then Vs[192][72]
    float* ams  = QV + QV4_FLOATS;            // [192]
    float* sstr = ams + 192;                  // [15][64]
    float* sinv = sstr + 15 * 64;             // [64]

    const int i0 = blockIdx.x * 64;
    const int bh = blockIdx.y;
    const int b  = bh >> 4;
    const int h  = bh & 15;

    const float* Qg  = g_Q + (size_t)bh * S_LEN * HDIM;
    const float* Vg  = g_V + (size_t)bh * S_LEN * HDIM;
    const float* amb = am + (size_t)b * S_LEN;

    const int j0   = (i0 >= 128) ? (i0 - 128) : 0;
    const int Wn   = i0 + 64 - j0;            // 64,128,192
    const int qoff = i0 - j0;                 // min(i0,128)
    const int nstr = (i0 >= 256) ? (i0 / 128 - 1) : 0;
    const int base = i0 & 127;                // 0 or 64 (strided residue base)

    const int tid = threadIdx.x;

    // ---- Q window -> smem (tf32), pitch 68; mask row -> smem ----
    for (int idx = tid; idx < Wn * 16; idx += 512) {
        int r = idx >> 4, c = (idx & 15) * 4;
        *(uint4*)&QV[r * QPITCH + c] =
            rna4(*(const float4*)&Qg[(size_t)(j0 + r) * HDIM + c]);
    }
    for (int idx = tid; idx < Wn; idx += 512) ams[idx] = amb[j0 + idx];
    __syncthreads();

    const int wid = tid >> 5, lane = tid & 31;
    const int g  = lane >> 2, lq = lane & 3;
    const int jgrp = wid >> 2, sb = wid & 3;
    const int r0 = jgrp * 16;
    const int t_lo = (qoff + r0 - 128) >> 3;
    const int rowA = qoff + r0 + g;
    const int NTW   = (sb < 2) ? 5 : 4;
    const int ubase = (sb < 2) ? sb * 5 : 10 + (sb - 2) * 4;

    const float* Qs = QV;

    // ---- phase A: S band tiles (5/5/4/4 per warp) -> compact P ----
    {
        float acc[5][4];
#pragma unroll
        for (int u = 0; u < 5; u++)
#pragma unroll
            for (int e = 0; e < 4; e++) acc[u][e] = 0.f;

#pragma unroll
        for (int kd = 0; kd < 8; kd++) {
            const int k = kd * 8 + lq;
            uint32_t a0 = __float_as_uint(Qs[rowA * QPITCH + k]);
            uint32_t a1 = __float_as_uint(Qs[(rowA + 8) * QPITCH + k]);
            uint32_t a2 = __float_as_uint(Qs[rowA * QPITCH + k + 4]);
            uint32_t a3 = __float_as_uint(Qs[(rowA + 8) * QPITCH + k + 4]);
#pragma unroll
            for (int u = 0; u < 5; u++) {
                const int t = t_lo + ubase + u;
                if (u < NTW && t >= 0) {
                    const int kr = t * 8 + g;
                    uint32_t b0 = __float_as_uint(Qs[kr * QPITCH + k]);
                    uint32_t b1 = __float_as_uint(Qs[kr * QPITCH + k + 4]);
                    MMA_TF32(acc[u], a0, a1, a2, a3, b0, b1);
                }
            }
        }
#pragma unroll
        for (int u = 0; u < 5; u++) {
            const int t = t_lo + ubase + u;
            if (u < NTW && t >= 0) {
                const int cabs = t * 8 + 2 * lq;           // window col
                const int cc   = (ubase + u) * 8 + 2 * lq; // compact col
                const float a0m = ams[cabs], a1m = ams[cabs + 1];
                float2 w0 = {acc[u][0] * 0.125f + a0m, acc[u][1] * 0.125f + a1m};
                float2 w1 = {acc[u][2] * 0.125f + a0m, acc[u][3] * 0.125f + a1m};
                *(float2*)&P[(r0 + g) * PPITCH4 + cc]     = w0;
                *(float2*)&P[(r0 + g + 8) * PPITCH4 + cc] = w1;
            }
        }
    }

    // ---- phase B: strided scores (8 lanes per row) ----
    const int rB  = tid >> 3;                 // 0..63
    const int qB8 = tid & 7;                  // 0..7
    {
        const float4* qp = (const float4*)&Qs[(qoff + rB) * QPITCH + qB8 * 8];
        const float4 qa = qp[0], qb = qp[1];  // loop-invariant, hoisted
        for (int k = 0; k < nstr; k++) {
            const int jb = base + rB + 128 * k;
            const float4* kp = (const float4*)&Qg[(size_t)jb * HDIM + qB8 * 8];
            float4 kb4 = kp[0];
            float s = qa.x * kb4.x + qa.y * kb4.y + qa.z * kb4.z + qa.w * kb4.w;
            float4 kc4 = kp[1];
            s += qb.x * kc4.x + qb.y * kc4.y + qb.z * kc4.z + qb.w * kc4.w;
            s += __shfl_xor_sync(0xFFFFFFFFu, s, 1);
            s += __shfl_xor_sync(0xFFFFFFFFu, s, 2);
            s += __shfl_xor_sync(0xFFFFFFFFu, s, 4);
            if (qB8 == 0) sstr[k * 64 + rB] = s * 0.125f + amb[jb];
        }
    }
    __syncthreads();

    // ---- V window -> smem (tf32), pitch 72 (hoisted; overlaps softmax) ----
    for (int idx = tid; idx < Wn * 16; idx += 512) {
        int r = idx >> 4, c = (idx & 15) * 4;
        *(uint4*)&QV[r * VPITCH4 + c] =
            rna4(*(const float4*)&Vg[(size_t)(j0 + r) * HDIM + c]);
    }

    // ---- phase C: softmax over compact band + strided ----
    {
        const int r   = rB;
        const int tlg = (qoff + (r & ~15) - 128) >> 3;
        const int off0 = max(0, qoff + r - 128) - tlg * 8;  // compact allowed lo
        const int off1 = (qoff + r) - tlg * 8;              // compact allowed hi
        const int vlo  = max(0, -tlg * 8);                  // first t>=0 col
        float* Pr = &P[r * PPITCH4];

        float mx = -1e30f;
        for (int c = off0 + ((qB8 - off0) & 7); c <= off1; c += 8)
            mx = fmaxf(mx, Pr[c]);
        for (int k = qB8; k < nstr; k += 8) mx = fmaxf(mx, sstr[k * 64 + r]);
        mx = fmaxf(mx, __shfl_xor_sync(0xFFFFFFFFu, mx, 1));
        mx = fmaxf(mx, __shfl_xor_sync(0xFFFFFFFFu, mx, 2));
        mx = fmaxf(mx, __shfl_xor_sync(0xFFFFFFFFu, mx, 4));

        float sum = 0.f;
        for (int c = vlo + ((qB8 - vlo) & 7); c < 144; c += 8) {
            float v = Pr[c];
            float p = (c >= off0 && c <= off1) ? __expf(v - mx) : 0.f;
            Pr[c] = __uint_as_float(rna1(p));
            sum += p;
        }
        for (int k = qB8; k < nstr; k += 8) {
            float p = __expf(sstr[k * 64 + r] - mx);
            sstr[k * 64 + r] = p;
            sum += p;
        }
        sum += __shfl_xor_sync(0xFFFFFFFFu, sum, 1);
        sum += __shfl_xor_sync(0xFFFFFFFFu, sum, 2);
        sum += __shfl_xor_sync(0xFFFFFFFFu, sum, 4);
        if (qB8 == 0) sinv[r] = 1.0f / sum;
    }
    __syncthreads();

    // ---- phase D: PV (2 n8-tiles per warp over 18 compact k-tiles) ----
    const float* Vs = QV;
    float oacc[2][4];
#pragma unroll
    for (int nt = 0; nt < 2; nt++)
#pragma unroll
        for (int e = 0; e < 4; e++) oacc[nt][e] = 0.f;

#pragma unroll
    for (int u = 0; u < 18; u++) {
        const int t = t_lo + u;
        if (t >= 0) {
            const int cc = u * 8;                 // compact k base
            const int kb = t * 8;                 // window k base
            uint32_t a0 = __float_as_uint(P[(r0 + g) * PPITCH4 + cc + lq]);
            uint32_t a1 = __float_as_uint(P[(r0 + g + 8) * PPITCH4 + cc + lq]);
            uint32_t a2 = __float_as_uint(P[(r0 + g) * PPITCH4 + cc + lq + 4]);
            uint32_t a3 = __float_as_uint(P[(r0 + g + 8) * PPITCH4 + cc + lq + 4]);
#pragma unroll
            for (int nt = 0; nt < 2; nt++) {
                const int ncol = sb * 16 + nt * 8 + g;
                uint32_t b0 = __float_as_uint(Vs[(kb + lq) * VPITCH4 + ncol]);
                uint32_t b1 = __float_as_uint(Vs[(kb + lq + 4) * VPITCH4 + ncol]);
                MMA_TF32(oacc[nt], a0, a1, a2, a3, b0, b1);
            }
        }
    }

    // strided PV (scalar, V from global fp32; warp covers its 16 cols)
    for (int k = 0; k < nstr; k++) {
        const float p0 = sstr[k * 64 + r0 + g];
        const float p1 = sstr[k * 64 + r0 + g + 8];
        const float* v0 = &Vg[(size_t)(base + r0 + g + 128 * k) * HDIM];
        const float* v1 = v0 + 8 * HDIM;
#pragma unroll
        for (int nt = 0; nt < 2; nt++) {
            const int n = sb * 16 + nt * 8 + 2 * lq;
            float2 x0 = *(const float2*)&v0[n];
            float2 x1 = *(const float2*)&v1[n];
            oacc[nt][0] += p0 * x0.x; oacc[nt][1] += p0 * x0.y;
            oacc[nt][2] += p1 * x1.x; oacc[nt][3] += p1 * x1.y;
        }
    }

    // ---- epilogue ----
    const float inv0 = sinv[r0 + g];
    const float inv1 = sinv[r0 + g + 8];
    const int iA = i0 + r0 + g;
    float* oA = &out[((size_t)(b * S_LEN + iA)) * HID + h * HDIM + sb * 16];
    float* oB = oA + 8 * HID;
#pragma unroll
    for (int nt = 0; nt < 2; nt++) {
        const int n = nt * 8 + 2 * lq;
        float2 w0 = {oacc[nt][0] * inv0, oacc[nt][1] * inv0};
        float2 w1 = {oacc[nt][2] * inv1, oacc[nt][3] * inv1};
        *(float2*)&oA[n] = w0;
        *(float2*)&oB[n] = w1;
    }
}

// ---------------------------------------------------------------------------
extern "C" void kernel_launch(void* const* d_in, const int* in_sizes, int n_in,
                              void* d_out, int out_size)
{
    const float* hidden = (const float*)d_in[0];
    const float* am     = (const float*)d_in[1];
    const float* Wq     = (const float*)d_in[2];
    const float* bq     = (const float*)d_in[3];
    const float* Wv     = (const float*)d_in[4];
    const float* bv     = (const float*)d_in[5];
    float* out = (float*)d_out;

    (void)in_sizes; (void)n_in; (void)out_size;

    cudaFuncSetAttribute(proj_mma,
                         cudaFuncAttributeMaxDynamicSharedMemorySize, PROJ_SMEM);
    cudaFuncSetAttribute(attn_mma,
                         cudaFuncAttributeMaxDynamicSharedMemorySize, ATTN4_SMEM);

    // fused tf32 rounding pre-pass
    conv_all_tf32<<<NT4 / 1024, 256>>>(hidden, Wq, Wv);

    dim3 gp(HID / 128, M_ROWS / 128, 2);
    proj_mma<<<gp, 256, PROJ_SMEM>>>(bq, bv);

    dim3 ga(S_LEN / 64, BH);
    attn_mma<<<ga, 512, ATTN4_SMEM>>>(am, out);
}